// round 13
// baseline (speedup 1.0000x reference)
#include <cuda_runtime.h>
#include <cuda_bf16.h>
#include <cstdint>

// Problem constants (fixed by reference):
//   g: (32, 16, 2048, 3) fp32, ar_phi: (3,3), ar_eta: (3,), ar_c: (3,)
//   P=3, KMAX=5 (11 windings), output: (32,) fp32
#define N_MC      32
#define N_SAMP    16
#define T_LEN     2048
#define TPRIME    2044                   // T - 1 - P
#define ROW_ELEMS (T_LEN * 3)            // 6144 floats
#define ROW_VEC4  (ROW_ELEMS / 4)        // 1536 float4s per row

#define CLUSTER   8                      // CTAs per cluster = per output m
#define SPC       2                      // samples per CTA (8*2 = 16 = N_SAMP)
#define GRID      (N_MC * CLUSTER)       // 256 CTAs, single wave
#define BLOCK     256
#define CHUNK     8                      // t-outputs per thread per sample

#define PI_F      3.14159265358979323846f
#define TWO_PI_F  6.28318530717958647693f
#define INV_2PI_F 0.15915494309189533577f

// Torus logmap: x - 2*pi*rint(x/2pi). Matches mod(x+pi,2pi)-pi except exact
// half-period boundaries (measure zero in fp32 data).
__device__ __forceinline__ float wrapf(float x) {
    return fmaf(-rintf(x * INV_2PI_F), TWO_PI_F, x);
}

__device__ __forceinline__ uint32_t smem_u32(const void* p) {
    uint32_t a;
    asm("{ .reg .u64 t; cvta.to.shared.u64 t, %1; cvt.u32.u64 %0, t; }"
        : "=r"(a) : "l"(p));
    return a;
}

__global__ __launch_bounds__(BLOCK) __cluster_dims__(CLUSTER, 1, 1)
void arp_cluster_kernel(const float* __restrict__ g,
                        const float* __restrict__ ar_phi,
                        const float* __restrict__ ar_eta,
                        const float* __restrict__ ar_c,
                        float* __restrict__ out) {
    __shared__ float sred[3][BLOCK / 32];
    __shared__ float slots[CLUSTER][3];   // leader CTA collects per-rank sums

    const int tid = threadIdx.x;
    const int m   = blockIdx.x / CLUSTER;
    uint32_t rank;
    asm("mov.u32 %0, %%cluster_ctarank;" : "=r"(rank));

    // Small params (L1-cached broadcast loads).
    float ph[3][3], cc[3];
#pragma unroll
    for (int d = 0; d < 3; d++) {
        ph[d][0] = __ldg(&ar_phi[d * 3 + 0]);
        ph[d][1] = __ldg(&ar_phi[d * 3 + 1]);
        ph[d][2] = __ldg(&ar_phi[d * 3 + 2]);
        cc[d]    = __ldg(&ar_c[d]);
    }

    const int t0   = tid * CHUNK;
    const int base = (3 * t0) >> 2;       // 3*t0 divisible by 4 (t0 % 8 == 0)
    const int row0 = m * N_SAMP + (int)rank * SPC;

    // ---- SINGLE front-batched memory exposure: BOTH sample-rows' 9 float4s
    // issued back-to-back (18 independent LDG.128 in flight per thread)
    // before any compute consumes them.
    const float4* g4a = reinterpret_cast<const float4*>(g)
                      + (size_t)row0 * ROW_VEC4;
    const float4* g4b = g4a + ROW_VEC4;
    float f0[36], f1[36];
#pragma unroll
    for (int k = 0; k < 9; k++) {
        int idx = base + k;
        if (idx > ROW_VEC4 - 1) idx = ROW_VEC4 - 1;   // tail clamp (unused data)
        float4 va = __ldg(&g4a[idx]);
        f0[4 * k + 0] = va.x; f0[4 * k + 1] = va.y;
        f0[4 * k + 2] = va.z; f0[4 * k + 3] = va.w;
    }
#pragma unroll
    for (int k = 0; k < 9; k++) {
        int idx = base + k;
        if (idx > ROW_VEC4 - 1) idx = ROW_VEC4 - 1;
        float4 vb = __ldg(&g4b[idx]);
        f1[4 * k + 0] = vb.x; f1[4 * k + 1] = vb.y;
        f1[4 * k + 2] = vb.z; f1[4 * k + 3] = vb.w;
    }

    // ---- AR(3) on wrapped first-diffs for both samples; each dx once.
    float acc[3] = {0.f, 0.f, 0.f};
#pragma unroll
    for (int s = 0; s < SPC; s++) {
        const float* f = (s == 0) ? f0 : f1;
#pragma unroll
        for (int d = 0; d < 3; d++) {
            float dx[CHUNK + 3];
#pragma unroll
            for (int j = 0; j < CHUNK + 3; j++)
                dx[j] = wrapf(f[3 * (j + 1) + d] - f[3 * j + d]);
            float ss = 0.f;
#pragma unroll
            for (int j = 0; j < CHUNK; j++) {
                float dyv = dx[j + 3] - (ph[d][0] * dx[j + 2]
                                       + ph[d][1] * dx[j + 1]
                                       + ph[d][2] * dx[j]);
                float u = dyv - cc[d];
                if (t0 + j < TPRIME) ss = fmaf(u, u, ss);
            }
            acc[d] += ss;
        }
    }

    // ---- Warp reduce, then 8-warp fold.
#pragma unroll
    for (int off = 16; off; off >>= 1)
#pragma unroll
        for (int d = 0; d < 3; d++)
            acc[d] += __shfl_xor_sync(0xffffffffu, acc[d], off);

    const int lane = tid & 31;
    const int warp = tid >> 5;
    if (lane == 0)
#pragma unroll
        for (int d = 0; d < 3; d++) sred[d][warp] = acc[d];
    __syncthreads();

    // ---- Leader's eta-dependent math is INDEPENDENT of peers' slots:
    // precompute the inverse-variances and the closed-form winding constant
    // BEFORE the cluster barrier so the post-barrier tail is just
    // 24 LDS + 6 FMA + 1 STG.
    //   sum_{k=-5..5} winding log-density collapses (sum k = 0, sum k^2 = 110)
    //   per (t,d) to: -5.5*u^2/var - 220*pi^2/var - 11*log(e) - 5.5*log(2*pi).
    // fp32 throughout: abs error ~1e4 vs tolerance budget ~8.5e7.
    float inv_var[3];
    float Cbase = 0.f;
    const bool is_leader = (rank == 0) && (tid == 0);
    if (is_leader) {
#pragma unroll
        for (int d = 0; d < 3; d++) {
            float e   = fabsf(__ldg(&ar_eta[d]));    // scale = sqrt(eta^2)
            float var = e * e;
            inv_var[d] = 1.0f / var;
            Cbase += (float)(N_SAMP * TPRIME) *
                     (-220.f * (PI_F * PI_F) / var - 11.f * logf(e)
                      - 5.5f * logf(TWO_PI_F));
        }
    }

    // ---- tid0 pushes this CTA's 3 sums into the LEADER CTA's slots via DSMEM.
    if (tid == 0) {
        float S[3];
#pragma unroll
        for (int d = 0; d < 3; d++) {
            float v = sred[d][0];
#pragma unroll
            for (int w = 1; w < BLOCK / 32; w++) v += sred[d][w];
            S[d] = v;
        }
        uint32_t laddr = smem_u32(&slots[rank][0]);   // same layout in every CTA
        uint32_t raddr;
        asm volatile("mapa.shared::cluster.u32 %0, %1, %2;"
                     : "=r"(raddr) : "r"(laddr), "r"(0u));   // -> leader (rank 0)
#pragma unroll
        for (int d = 0; d < 3; d++)
            asm volatile("st.shared::cluster.f32 [%0], %1;"
                         :: "r"(raddr + 4u * d), "f"(S[d]) : "memory");
    }

    // Cluster barrier: release DSMEM stores, then leader may read.
    asm volatile("barrier.cluster.arrive.aligned;" ::: "memory");
    asm volatile("barrier.cluster.wait.aligned;" ::: "memory");

    // ---- Leader: minimal tail — fold 8 ranks with precomputed factors.
    if (is_leader) {
        float res = Cbase;
#pragma unroll
        for (int d = 0; d < 3; d++) {
            float Sd = slots[0][d];
#pragma unroll
            for (int r = 1; r < CLUSTER; r++) Sd += slots[r][d];
            res = fmaf(-5.5f * Sd, inv_var[d], res);
        }
        out[m] = res;
    }
}

extern "C" void kernel_launch(void* const* d_in, const int* in_sizes, int n_in,
                              void* d_out, int out_size) {
    const float* g      = (const float*)d_in[0];
    const float* ar_phi = (const float*)d_in[1];
    const float* ar_eta = (const float*)d_in[2];
    const float* ar_c   = (const float*)d_in[3];
    float* out = (float*)d_out;

    arp_cluster_kernel<<<GRID, BLOCK>>>(g, ar_phi, ar_eta, ar_c, out);
}